// round 2
// baseline (speedup 1.0000x reference)
#include <cuda_runtime.h>
#include <cstdint>

// TranVectorQuantizer: latent [16384,8,32] f32, codebook [128,32] f32.
// Outputs concatenated in d_out (all f32):
//   [0,        4194304)  policy_vq_latent = latent + (quantized - latent)
//   [4194304,  8388608)  quantized_latent = codebook[argmin_j dist(x, c_j)]
//   [8388608, 75497472)  codebook_set = codebook tiled 16384x (contiguous 4096-float tiles)
//
// Distance is computed EXACTLY in the reference's arithmetic shape:
//   d_j = fl( fl(A + B_j) - 2*M_j ),  A=sum(x^2), B_j=sum(c_j^2), M_j=x.c_j (fp32)
// The +A term snaps distances to a ~ulp(32) grid, creating exact ties that
// argmin breaks toward the lower index; we must reproduce that snapping.

#define DDIM 32
#define KCODES 128

static __device__ __forceinline__ unsigned long long pk2(float a, float b) {
    unsigned long long r;
    asm("mov.b64 %0, {%1, %2};" : "=l"(r) : "f"(a), "f"(b));
    return r;
}

__global__ void __launch_bounds__(256) vq_fused_kernel(
    const float* __restrict__ latent,
    const float* __restrict__ cb,
    float* __restrict__ out,
    int n_rows)
{
    __shared__ float s_cb[KCODES * DDIM];   // 16 KB
    __shared__ float s_nrm[KCODES];         // B_j = ||c_j||^2 (fp32)

    const int tid  = threadIdx.x;
    const int gtid = blockIdx.x * 256 + tid;

    // ---- stage codebook into smem (coalesced float4) ----
    float4* s_cb4 = reinterpret_cast<float4*>(s_cb);
    const float4* cb4 = reinterpret_cast<const float4*>(cb);
    #pragma unroll
    for (int i = 0; i < 4; i++) s_cb4[tid + i * 256] = cb4[tid + i * 256];
    __syncthreads();

    if (tid < KCODES) {
        float s = 0.f;
        #pragma unroll
        for (int d = 0; d < DDIM; d++) {
            float v = s_cb[tid * DDIM + d];
            s += v * v;
        }
        s_nrm[tid] = s;
    }
    __syncthreads();

    const size_t n_lat = (size_t)n_rows * DDIM;        // 4194304
    float* out_policy = out;
    float* out_quant  = out + n_lat;
    float4* out_cs4   = reinterpret_cast<float4*>(out + 2 * n_lat);

    // ---- broadcast codebook_set: tiled copies of the 4096-float codebook ----
    {
        const size_t total4 = (size_t)n_rows * 128;            // float4 count
        const size_t nth    = (size_t)gridDim.x * blockDim.x;
        if ((nth & 1023) == 0) {
            // stride preserves (i4 & 1023): hoist the smem read, stream stores
            float4 v = s_cb4[(size_t)gtid & 1023];
            #pragma unroll 8
            for (size_t i4 = (size_t)gtid; i4 < total4; i4 += nth)
                __stcs(&out_cs4[i4], v);
        } else {
            for (size_t i4 = (size_t)gtid; i4 < total4; i4 += nth)
                __stcs(&out_cs4[i4], s_cb4[i4 & 1023]);
        }
    }

    // ---- VQ: one row per thread ----
    if (gtid < n_rows) {
        const float* xr = latent + (size_t)gtid * DDIM;
        float4 xv[8];
        const float4* xr4 = reinterpret_cast<const float4*>(xr);
        #pragma unroll
        for (int k = 0; k < 8; k++) xv[k] = xr4[k];

        // A = ||x||^2 (fp32; exact order is uniform-shift-invariant across j)
        float A;
        {
            float a0 = 0.f, a1 = 0.f, a2 = 0.f, a3 = 0.f;
            #pragma unroll
            for (int k = 0; k < 8; k++) {
                a0 = fmaf(xv[k].x, xv[k].x, a0);
                a1 = fmaf(xv[k].y, xv[k].y, a1);
                a2 = fmaf(xv[k].z, xv[k].z, a2);
                a3 = fmaf(xv[k].w, xv[k].w, a3);
            }
            A = (a0 + a1) + (a2 + a3);
        }

        // pack row into f32x2 operands
        unsigned long long xp0[8], xp1[8];
        #pragma unroll
        for (int k = 0; k < 8; k++) {
            xp0[k] = pk2(xv[k].x, xv[k].y);
            xp1[k] = pk2(xv[k].z, xv[k].w);
        }

        float best = 3.0e38f;
        int   bi   = 0;
        const ulonglong2* scb2 = reinterpret_cast<const ulonglong2*>(s_cb);

        #pragma unroll 2
        for (int j = 0; j < KCODES; j++) {
            unsigned long long acc0 = 0ull, acc1 = 0ull;
            const ulonglong2* cj = scb2 + j * 8;   // 8 x 16B per code (broadcast LDS)
            #pragma unroll
            for (int k = 0; k < 8; k++) {
                ulonglong2 c = cj[k];
                asm("fma.rn.f32x2 %0, %1, %2, %0;" : "+l"(acc0) : "l"(xp0[k]), "l"(c.x));
                asm("fma.rn.f32x2 %0, %1, %2, %0;" : "+l"(acc1) : "l"(xp1[k]), "l"(c.y));
            }
            unsigned long long accs;
            asm("add.rn.f32x2 %0, %1, %2;" : "=l"(accs) : "l"(acc0), "l"(acc1));
            float lo, hi;
            asm("mov.b64 {%0, %1}, %2;" : "=f"(lo), "=f"(hi) : "l"(accs));
            float M = lo + hi;                       // x . c_j  (fp32)
            float S = A + s_nrm[j];                  // fl(A + B_j)  -- the snapping add
            float d = fmaf(-2.0f, M, S);             // fl(S - 2M), single rounding
            if (d < best) { best = d; bi = j; }      // strict < keeps first (lowest) index
        }

        // gather winning code, write quantized and policy (= x + (q - x), as reference)
        const float4* q4 = reinterpret_cast<const float4*>(s_cb + bi * DDIM);
        float4* oq = reinterpret_cast<float4*>(out_quant  + (size_t)gtid * DDIM);
        float4* op = reinterpret_cast<float4*>(out_policy + (size_t)gtid * DDIM);
        #pragma unroll
        for (int k = 0; k < 8; k++) {
            float4 q = q4[k];
            oq[k] = q;
            float4 x = xv[k];
            float4 p;
            p.x = x.x + (q.x - x.x);
            p.y = x.y + (q.y - x.y);
            p.z = x.z + (q.z - x.z);
            p.w = x.w + (q.w - x.w);
            op[k] = p;
        }
    }
}

extern "C" void kernel_launch(void* const* d_in, const int* in_sizes, int n_in,
                              void* d_out, int out_size)
{
    const float* latent = (const float*)d_in[0];
    const float* cb     = (const float*)d_in[1];
    int sz0 = in_sizes[0], sz1 = in_sizes[1];
    if (sz0 < sz1) {  // safety: latent is the big tensor
        const float* t = latent; latent = cb; cb = t;
        int ts = sz0; sz0 = sz1; sz1 = ts;
    }
    (void)n_in; (void)out_size;
    int n_rows = sz0 / DDIM;            // 131072
    int blocks = (n_rows + 255) / 256;  // 512
    vq_fused_kernel<<<blocks, 256>>>(latent, cb, (float*)d_out, n_rows);
}

// round 3
// speedup vs baseline: 1.0003x; 1.0003x over previous
#include <cuda_runtime.h>
#include <cstdint>

// TranVectorQuantizer: latent [16384,8,32] f32, codebook [128,32] f32.
// Outputs concatenated in d_out (all f32):
//   [0,        4194304)  policy_vq_latent = latent + (quantized - latent)
//   [4194304,  8388608)  quantized_latent = codebook[argmin_j dist(x, c_j)]
//   [8388608, 75497472)  codebook_set = codebook tiled 16384x (contiguous 4096-float tiles)
//
// Distance is computed EXACTLY in the reference's arithmetic shape:
//   d_j = fl( fl(A + B_j) - 2*M_j ),  A=sum(x^2), B_j=sum(c_j^2), M_j=x.c_j (fp32)
// The +A term snaps distances to a ~ulp(32) grid, creating exact ties that
// argmin breaks toward the lower index; we must reproduce that snapping.

#define DDIM 32
#define KCODES 128

static __device__ __forceinline__ unsigned long long pk2(float a, float b) {
    unsigned long long r;
    asm("mov.b64 %0, {%1, %2};" : "=l"(r) : "f"(a), "f"(b));
    return r;
}

__global__ void __launch_bounds__(256) vq_fused_kernel(
    const float* __restrict__ latent,
    const float* __restrict__ cb,
    float* __restrict__ out,
    int n_rows)
{
    __shared__ float s_cb[KCODES * DDIM];   // 16 KB
    __shared__ float s_nrm[KCODES];         // B_j = ||c_j||^2 (fp32)

    const int tid  = threadIdx.x;
    const int gtid = blockIdx.x * 256 + tid;

    // ---- stage codebook into smem (coalesced float4) ----
    float4* s_cb4 = reinterpret_cast<float4*>(s_cb);
    const float4* cb4 = reinterpret_cast<const float4*>(cb);
    #pragma unroll
    for (int i = 0; i < 4; i++) s_cb4[tid + i * 256] = cb4[tid + i * 256];
    __syncthreads();

    if (tid < KCODES) {
        float s = 0.f;
        #pragma unroll
        for (int d = 0; d < DDIM; d++) {
            float v = s_cb[tid * DDIM + d];
            s += v * v;
        }
        s_nrm[tid] = s;
    }
    __syncthreads();

    const size_t n_lat = (size_t)n_rows * DDIM;        // 4194304
    float* out_policy = out;
    float* out_quant  = out + n_lat;
    float4* out_cs4   = reinterpret_cast<float4*>(out + 2 * n_lat);

    // ---- broadcast codebook_set: tiled copies of the 4096-float codebook ----
    {
        const size_t total4 = (size_t)n_rows * 128;            // float4 count
        const size_t nth    = (size_t)gridDim.x * blockDim.x;
        if ((nth & 1023) == 0) {
            // stride preserves (i4 & 1023): hoist the smem read, stream stores
            float4 v = s_cb4[(size_t)gtid & 1023];
            #pragma unroll 8
            for (size_t i4 = (size_t)gtid; i4 < total4; i4 += nth)
                __stcs(&out_cs4[i4], v);
        } else {
            for (size_t i4 = (size_t)gtid; i4 < total4; i4 += nth)
                __stcs(&out_cs4[i4], s_cb4[i4 & 1023]);
        }
    }

    // ---- VQ: one row per thread ----
    if (gtid < n_rows) {
        const float* xr = latent + (size_t)gtid * DDIM;
        float4 xv[8];
        const float4* xr4 = reinterpret_cast<const float4*>(xr);
        #pragma unroll
        for (int k = 0; k < 8; k++) xv[k] = xr4[k];

        // A = ||x||^2 (fp32; exact order is uniform-shift-invariant across j)
        float A;
        {
            float a0 = 0.f, a1 = 0.f, a2 = 0.f, a3 = 0.f;
            #pragma unroll
            for (int k = 0; k < 8; k++) {
                a0 = fmaf(xv[k].x, xv[k].x, a0);
                a1 = fmaf(xv[k].y, xv[k].y, a1);
                a2 = fmaf(xv[k].z, xv[k].z, a2);
                a3 = fmaf(xv[k].w, xv[k].w, a3);
            }
            A = (a0 + a1) + (a2 + a3);
        }

        // pack row into f32x2 operands
        unsigned long long xp0[8], xp1[8];
        #pragma unroll
        for (int k = 0; k < 8; k++) {
            xp0[k] = pk2(xv[k].x, xv[k].y);
            xp1[k] = pk2(xv[k].z, xv[k].w);
        }

        float best = 3.0e38f;
        int   bi   = 0;
        const ulonglong2* scb2 = reinterpret_cast<const ulonglong2*>(s_cb);

        #pragma unroll 2
        for (int j = 0; j < KCODES; j++) {
            unsigned long long acc0 = 0ull, acc1 = 0ull;
            const ulonglong2* cj = scb2 + j * 8;   // 8 x 16B per code (broadcast LDS)
            #pragma unroll
            for (int k = 0; k < 8; k++) {
                ulonglong2 c = cj[k];
                asm("fma.rn.f32x2 %0, %1, %2, %0;" : "+l"(acc0) : "l"(xp0[k]), "l"(c.x));
                asm("fma.rn.f32x2 %0, %1, %2, %0;" : "+l"(acc1) : "l"(xp1[k]), "l"(c.y));
            }
            unsigned long long accs;
            asm("add.rn.f32x2 %0, %1, %2;" : "=l"(accs) : "l"(acc0), "l"(acc1));
            float lo, hi;
            asm("mov.b64 {%0, %1}, %2;" : "=f"(lo), "=f"(hi) : "l"(accs));
            float M = lo + hi;                       // x . c_j  (fp32)
            float S = A + s_nrm[j];                  // fl(A + B_j)  -- the snapping add
            float d = fmaf(-2.0f, M, S);             // fl(S - 2M), single rounding
            if (d < best) { best = d; bi = j; }      // strict < keeps first (lowest) index
        }

        // gather winning code, write quantized and policy (= x + (q - x), as reference)
        const float4* q4 = reinterpret_cast<const float4*>(s_cb + bi * DDIM);
        float4* oq = reinterpret_cast<float4*>(out_quant  + (size_t)gtid * DDIM);
        float4* op = reinterpret_cast<float4*>(out_policy + (size_t)gtid * DDIM);
        #pragma unroll
        for (int k = 0; k < 8; k++) {
            float4 q = q4[k];
            oq[k] = q;
            float4 x = xv[k];
            float4 p;
            p.x = x.x + (q.x - x.x);
            p.y = x.y + (q.y - x.y);
            p.z = x.z + (q.z - x.z);
            p.w = x.w + (q.w - x.w);
            op[k] = p;
        }
    }
}

extern "C" void kernel_launch(void* const* d_in, const int* in_sizes, int n_in,
                              void* d_out, int out_size)
{
    const float* latent = (const float*)d_in[0];
    const float* cb     = (const float*)d_in[1];
    int sz0 = in_sizes[0], sz1 = in_sizes[1];
    if (sz0 < sz1) {  // safety: latent is the big tensor
        const float* t = latent; latent = cb; cb = t;
        int ts = sz0; sz0 = sz1; sz1 = ts;
    }
    (void)n_in; (void)out_size;
    int n_rows = sz0 / DDIM;            // 131072
    int blocks = (n_rows + 255) / 256;  // 512
    vq_fused_kernel<<<blocks, 256>>>(latent, cb, (float*)d_out, n_rows);
}

// round 4
// speedup vs baseline: 1.6200x; 1.6195x over previous
#include <cuda_runtime.h>
#include <cstdint>

// TranVectorQuantizer: latent [16384,8,32] f32, codebook [128,32] f32.
// Outputs concatenated in d_out (all f32):
//   [0,        4194304)  policy_vq_latent = latent + (quantized - latent)
//   [4194304,  8388608)  quantized_latent = codebook[argmin_j dist(x, c_j)]
//   [8388608, 75497472)  codebook_set = codebook tiled 16384x
//
// Distance reproduces the reference arithmetic EXACTLY (passed rel_err 0.0):
//   d_j = fmaf(-2, M_j, fl(A + B_j)),  fixed accumulation order for M_j.
// DO NOT change the FMA chain order: the +A add snaps distances to a
// ~ulp(32) grid and tie-breaking depends on it.
//
// Perf structure: codebook_set broadcast stores are interleaved 1:1 with the
// 128 argmin iterations so DRAM write drain overlaps the latency-bound
// FFMA2/LDS chains instead of serializing into two chip-wide phases.

#define DDIM 32
#define KCODES 128
#define TPB 128

static __device__ __forceinline__ unsigned long long pk2(float a, float b) {
    unsigned long long r;
    asm("mov.b64 %0, {%1, %2};" : "=l"(r) : "f"(a), "f"(b));
    return r;
}
static __device__ __forceinline__ void upk2(unsigned long long p, float& a, float& b) {
    asm("mov.b64 {%0, %1}, %2;" : "=f"(a), "=f"(b) : "l"(p));
}

__global__ void __launch_bounds__(TPB, 8) vq_fused_kernel(
    const float* __restrict__ latent,
    const float* __restrict__ cb,
    float* __restrict__ out,
    int n_rows, int exact)
{
    __shared__ float s_cb[KCODES * DDIM];   // 16 KB
    __shared__ float s_nrm[KCODES];         // B_j = ||c_j||^2

    const int tid  = threadIdx.x;
    const int gtid = blockIdx.x * TPB + tid;
    const bool active = gtid < n_rows;

    // ---- issue latent loads early (overlap codebook staging) ----
    float4 xv[8];
    const float4* xr4 = reinterpret_cast<const float4*>(latent) + (size_t)gtid * 8;
    if (active) {
        #pragma unroll
        for (int k = 0; k < 8; k++) xv[k] = xr4[k];
    }

    // ---- stage codebook into smem ----
    float4* s_cb4 = reinterpret_cast<float4*>(s_cb);
    const float4* cb4 = reinterpret_cast<const float4*>(cb);
    #pragma unroll
    for (int i = 0; i < 8; i++) s_cb4[tid + i * TPB] = cb4[tid + i * TPB];
    __syncthreads();

    // TPB == KCODES: one norm per thread (same order as passing version)
    {
        float s = 0.f;
        #pragma unroll
        for (int d = 0; d < DDIM; d++) {
            float v = s_cb[tid * DDIM + d];
            s += v * v;
        }
        s_nrm[tid] = s;
    }
    __syncthreads();

    const size_t n_lat = (size_t)n_rows * DDIM;
    float* out_quant = out + n_lat;
    float4* out_cs4  = reinterpret_cast<float4*>(out + 2 * n_lat);
    const size_t nth = (size_t)gridDim.x * blockDim.x;

    // ---- pack row + A = ||x||^2 (identical numerics to passing version) ----
    unsigned long long xp0[8], xp1[8];
    float A = 0.f;
    if (active) {
        float a0 = 0.f, a1 = 0.f, a2 = 0.f, a3 = 0.f;
        #pragma unroll
        for (int k = 0; k < 8; k++) {
            a0 = fmaf(xv[k].x, xv[k].x, a0);
            a1 = fmaf(xv[k].y, xv[k].y, a1);
            a2 = fmaf(xv[k].z, xv[k].z, a2);
            a3 = fmaf(xv[k].w, xv[k].w, a3);
            xp0[k] = pk2(xv[k].x, xv[k].y);
            xp1[k] = pk2(xv[k].z, xv[k].w);
        }
        A = (a0 + a1) + (a2 + a3);
    }
    // xv dead from here; policy x recovered from xp later (bit-identical).

    float best = 3.0e38f;
    int   bi   = 0;
    const ulonglong2* scb2 = reinterpret_cast<const ulonglong2*>(s_cb);

    if (exact) {
        // nth == n_rows, nth % 1024 == 0: every thread owns a fixed broadcast
        // value and writes it once per argmin iteration.
        float4 vbc = s_cb4[gtid & 1023];
        float4* csp = out_cs4 + gtid;

        #pragma unroll 2
        for (int j = 0; j < KCODES; j++) {
            __stcs(csp, vbc);          // interleaved codebook_set store
            csp += nth;

            unsigned long long acc0 = 0ull, acc1 = 0ull;
            const ulonglong2* cj = scb2 + j * 8;
            #pragma unroll
            for (int k = 0; k < 8; k++) {
                ulonglong2 c = cj[k];
                asm("fma.rn.f32x2 %0, %1, %2, %0;" : "+l"(acc0) : "l"(xp0[k]), "l"(c.x));
                asm("fma.rn.f32x2 %0, %1, %2, %0;" : "+l"(acc1) : "l"(xp1[k]), "l"(c.y));
            }
            unsigned long long accs;
            asm("add.rn.f32x2 %0, %1, %2;" : "=l"(accs) : "l"(acc0), "l"(acc1));
            float lo, hi; upk2(accs, lo, hi);
            float M = lo + hi;                  // x . c_j
            float S = A + s_nrm[j];             // snapping add
            float d = fmaf(-2.0f, M, S);        // single rounding
            if (d < best) { best = d; bi = j; } // strict <: first index on ties
        }
    } else {
        // generic fallback: separate broadcast loop, then VQ (same numerics)
        const size_t total4 = (size_t)n_rows * 128;
        for (size_t i4 = (size_t)gtid; i4 < total4; i4 += nth)
            __stcs(&out_cs4[i4], s_cb4[i4 & 1023]);

        if (active) {
            #pragma unroll 2
            for (int j = 0; j < KCODES; j++) {
                unsigned long long acc0 = 0ull, acc1 = 0ull;
                const ulonglong2* cj = scb2 + j * 8;
                #pragma unroll
                for (int k = 0; k < 8; k++) {
                    ulonglong2 c = cj[k];
                    asm("fma.rn.f32x2 %0, %1, %2, %0;" : "+l"(acc0) : "l"(xp0[k]), "l"(c.x));
                    asm("fma.rn.f32x2 %0, %1, %2, %0;" : "+l"(acc1) : "l"(xp1[k]), "l"(c.y));
                }
                unsigned long long accs;
                asm("add.rn.f32x2 %0, %1, %2;" : "=l"(accs) : "l"(acc0), "l"(acc1));
                float lo, hi; upk2(accs, lo, hi);
                float M = lo + hi;
                float S = A + s_nrm[j];
                float d = fmaf(-2.0f, M, S);
                if (d < best) { best = d; bi = j; }
            }
        }
    }

    // ---- write quantized + policy (policy x unpacked from xp: bit-identical) ----
    if (active) {
        const float4* q4 = reinterpret_cast<const float4*>(s_cb + bi * DDIM);
        float4* oq = reinterpret_cast<float4*>(out_quant) + (size_t)gtid * 8;
        float4* op = reinterpret_cast<float4*>(out)       + (size_t)gtid * 8;
        #pragma unroll
        for (int k = 0; k < 8; k++) {
            float4 q = q4[k];
            __stcs(oq + k, q);
            float xx, xy, xz, xw;
            upk2(xp0[k], xx, xy);
            upk2(xp1[k], xz, xw);
            float4 p;
            p.x = xx + (q.x - xx);
            p.y = xy + (q.y - xy);
            p.z = xz + (q.z - xz);
            p.w = xw + (q.w - xw);
            __stcs(op + k, p);
        }
    }
}

extern "C" void kernel_launch(void* const* d_in, const int* in_sizes, int n_in,
                              void* d_out, int out_size)
{
    const float* latent = (const float*)d_in[0];
    const float* cb     = (const float*)d_in[1];
    int sz0 = in_sizes[0], sz1 = in_sizes[1];
    if (sz0 < sz1) {  // safety: latent is the big tensor
        const float* t = latent; latent = cb; cb = t;
        int ts = sz0; sz0 = sz1; sz1 = ts;
    }
    (void)n_in; (void)out_size;
    int n_rows = sz0 / DDIM;                 // 131072
    int blocks = (n_rows + TPB - 1) / TPB;   // 1024
    size_t nth = (size_t)blocks * TPB;
    int exact = (nth == (size_t)n_rows) && ((nth & 1023) == 0);
    vq_fused_kernel<<<blocks, TPB>>>(latent, cb, (float*)d_out, n_rows, exact);
}